// round 6
// baseline (speedup 1.0000x reference)
#include <cuda_runtime.h>
#include <cuda_fp16.h>
#include <cuda_pipeline.h>

#define T    512
#define K    4
#define G    20000
#define EPG  3
#define B    512

#define BT     32                  // batches per tile (= lanes)
#define NBT    (B / BT)            // 16
#define BLKG   1024                // gather threads: 32 warps
#define GPB    256                 // g per chunk
#define NCHUNK 81                  // 81*256 = 20736 >= 20000; 81 = 9 splits x 9 chunks
#define GPAD   (NCHUNK * GPB)      // 20736
#define NSPLIT 9                   // gather blocks per bt: 16*9 = 144 ~= 1 wave
#define BLKP   512                 // prep threads

// h2 fp16, layout [bt][t][b_in] as uint2 (k0k1, k2k3): 2 MB, L2-resident.
__device__ uint2  g_h2u[NBT * T * BT];
// per-g 64B records: q0={e0*32,e1*32,e2*32,b3}, q1..q3 = w3[12]
__device__ float4 g_grec[GPAD * 4];

__device__ __forceinline__ float leaky(float x) {
    return x > 0.0f ? x : 0.01f * x;
}

// Packed f32x2 FMA (Blackwell FFMA2) — bit-identical to two scalar fp32 FMAs.
__device__ __forceinline__ float2 ffma2(float2 a, float2 b, float2 c) {
    float2 d;
    asm("{\n\t"
        ".reg .b64 ra, rb, rc, rd;\n\t"
        "mov.b64 ra, {%2, %3};\n\t"
        "mov.b64 rb, {%4, %5};\n\t"
        "mov.b64 rc, {%6, %7};\n\t"
        "fma.rn.f32x2 rd, ra, rb, rc;\n\t"
        "mov.b64 {%0, %1}, rd;\n\t"
        "}"
        : "=f"(d.x), "=f"(d.y)
        : "f"(a.x), "f"(a.y), "f"(b.x), "f"(b.y), "f"(c.x), "f"(c.y));
    return d;
}

// ---------------------------------------------------------------------------
// Fused prep kernel. Blocks [0, 512): h2 compute. Rest: pack records.
// ---------------------------------------------------------------------------
#define H2_BLOCKS   512
#define PACK_ITEMS  (GPAD * 4)                         // 82944 record quarters
#define PACK_BLOCKS ((PACK_ITEMS + BLKP - 1) / BLKP)   // 162

__global__ void prep_kernel(const float*  __restrict__ features,
                            const float4* __restrict__ w1,
                            const float4* __restrict__ b1,
                            const float4* __restrict__ w2,
                            const float4* __restrict__ b2,
                            const int*    __restrict__ edge,
                            const float*  __restrict__ w3,
                            const float*  __restrict__ b3) {
    const int tid = threadIdx.x;
    if (blockIdx.x < H2_BLOCKS) {
        const int b_in = tid & 31;
        const int ty   = tid >> 5;
        const int bt   = blockIdx.x & (NBT - 1);
        const int t    = (blockIdx.x >> 4) * 16 + ty;
        const int b    = bt * BT + b_in;

        const float  f   = features[b * T + t];
        const float4 w1v = w1[t];
        const float4 b1v = b1[t];
        const float4 b2v = b2[t];

        const float h0 = leaky(fmaf(f, w1v.x, b1v.x));
        const float h1 = leaky(fmaf(f, w1v.y, b1v.y));
        const float h2 = leaky(fmaf(f, w1v.z, b1v.z));
        const float h3 = leaky(fmaf(f, w1v.w, b1v.w));

        const float4 w20 = w2[t * 4 + 0];
        const float4 w21 = w2[t * 4 + 1];
        const float4 w22 = w2[t * 4 + 2];
        const float4 w23 = w2[t * 4 + 3];

        float4 o;
        o.x = leaky(fmaf(h3, w23.x, fmaf(h2, w22.x, fmaf(h1, w21.x, fmaf(h0, w20.x, b2v.x)))));
        o.y = leaky(fmaf(h3, w23.y, fmaf(h2, w22.y, fmaf(h1, w21.y, fmaf(h0, w20.y, b2v.y)))));
        o.z = leaky(fmaf(h3, w23.z, fmaf(h2, w22.z, fmaf(h1, w21.z, fmaf(h0, w20.z, b2v.z)))));
        o.w = leaky(fmaf(h3, w23.w, fmaf(h2, w22.w, fmaf(h1, w21.w, fmaf(h0, w20.w, b2v.w)))));

        const __half2 p0 = __floats2half2_rn(o.x, o.y);
        const __half2 p1 = __floats2half2_rn(o.z, o.w);
        uint2 p;
        p.x = *reinterpret_cast<const unsigned int*>(&p0);
        p.y = *reinterpret_cast<const unsigned int*>(&p1);
        g_h2u[((size_t)bt * T + t) * BT + b_in] = p;
    } else {
        const int i = (blockIdx.x - H2_BLOCKS) * BLKP + tid;
        if (i >= PACK_ITEMS) return;
        const int g    = i >> 2;
        const int part = i & 3;
        float4 q = make_float4(0.f, 0.f, 0.f, 0.f);
        if (g < G) {
            if (part == 0) {
                q = make_float4(__int_as_float(edge[3 * g + 0] * BT),
                                __int_as_float(edge[3 * g + 1] * BT),
                                __int_as_float(edge[3 * g + 2] * BT),
                                b3[g]);
            } else {
                q = reinterpret_cast<const float4*>(w3)[g * 3 + part - 1];
            }
        }
        g_grec[i] = q;
    }
}

// ---------------------------------------------------------------------------
// Gather: persistent h2 tile + double-buffered record chunks + smem out tile.
// smem: h2 128KB | rec 2x16KB | out 32KB = 192KB, 1024 threads.
// Inner loop software-pipelined: next g's (q0 -> h2) chain overlaps current FMAs.
// ---------------------------------------------------------------------------
#define SM_H2   0
#define SM_REC  131072
#define SM_OUT  (131072 + 32768)

__global__ void __launch_bounds__(BLKG, 1)
gather_kernel(float* __restrict__ out) {
    extern __shared__ char smem_raw[];
    uint2*  s_h2  = reinterpret_cast<uint2*>(smem_raw + SM_H2);    // [T*BT]
    float4* s_rec = reinterpret_cast<float4*>(smem_raw + SM_REC);  // [2][GPB*4]
    float*  s_out = reinterpret_cast<float*>(smem_raw + SM_OUT);   // [GPB*32]

    const int tid  = threadIdx.x;
    const int bt   = blockIdx.y;
    const int w    = tid >> 5;
    const int lane = tid & 31;

    // Stage persistent h2 tile (8192 x 16B) + first record chunk.
    {
        const uint4* src = reinterpret_cast<const uint4*>(g_h2u + (size_t)bt * T * BT);
        uint4*       dst = reinterpret_cast<uint4*>(s_h2);
        #pragma unroll
        for (int i = tid; i < T * BT / 2; i += BLKG)
            __pipeline_memcpy_async(&dst[i], &src[i], 16);
    }
    int c = blockIdx.x;   // first chunk for this split
    {
        const float4* rsrc = g_grec + (size_t)c * GPB * 4;
        #pragma unroll
        for (int i = tid; i < GPB * 4; i += BLKG)
            __pipeline_memcpy_async(&s_rec[i], &rsrc[i], 16);
    }
    __pipeline_commit();
    __pipeline_wait_prior(0);
    __syncthreads();

    const uint2* s_h2_lane = s_h2 + lane;

    int buf = 0;
    #pragma unroll 1
    for (int iter = 0; iter < NCHUNK / NSPLIT; iter++) {   // exactly 9 chunks/split
        const int  cn       = c + NSPLIT;
        const bool has_next = (iter + 1 < NCHUNK / NSPLIT);

        if (has_next) {
            const float4* rsrc = g_grec + (size_t)cn * GPB * 4;
            float4*       rdst = s_rec + (buf ^ 1) * GPB * 4;
            #pragma unroll
            for (int i = tid; i < GPB * 4; i += BLKG)
                __pipeline_memcpy_async(&rdst[i], &rsrc[i], 16);
            __pipeline_commit();
        }

        // Compute: warp w owns g_local in [w*8, w*8+8); lane = batch.
        // Software pipelined: prefetch next g's q0 + h2 rows during current FMAs.
        {
            const float4* rec = s_rec + buf * GPB * 4;
            const int gl0 = w * 8;

            float4 q0 = rec[gl0 * 4];
            uint2 p0 = s_h2_lane[__float_as_int(q0.x)];
            uint2 p1 = s_h2_lane[__float_as_int(q0.y)];
            uint2 p2 = s_h2_lane[__float_as_int(q0.z)];

            #pragma unroll
            for (int gg = 0; gg < 8; gg++) {
                const int gl = gl0 + gg;

                const float bias = q0.w;
                const uint2 c0 = p0, c1 = p1, c2 = p2;

                if (gg < 7) {   // prefetch next g
                    q0 = rec[(gl + 1) * 4];
                    p0 = s_h2_lane[__float_as_int(q0.x)];
                    p1 = s_h2_lane[__float_as_int(q0.y)];
                    p2 = s_h2_lane[__float_as_int(q0.z)];
                }

                const float4 q1 = rec[gl * 4 + 1];
                const float4 q2 = rec[gl * 4 + 2];
                const float4 q3 = rec[gl * 4 + 3];

                float2 acc0 = make_float2(bias, 0.f);
                float2 acc1 = make_float2(0.f, 0.f);

                acc0 = ffma2(__half22float2(*reinterpret_cast<const __half2*>(&c0.x)),
                             make_float2(q1.x, q1.y), acc0);
                acc1 = ffma2(__half22float2(*reinterpret_cast<const __half2*>(&c0.y)),
                             make_float2(q1.z, q1.w), acc1);
                acc0 = ffma2(__half22float2(*reinterpret_cast<const __half2*>(&c1.x)),
                             make_float2(q2.x, q2.y), acc0);
                acc1 = ffma2(__half22float2(*reinterpret_cast<const __half2*>(&c1.y)),
                             make_float2(q2.z, q2.w), acc1);
                acc0 = ffma2(__half22float2(*reinterpret_cast<const __half2*>(&c2.x)),
                             make_float2(q3.x, q3.y), acc0);
                acc1 = ffma2(__half22float2(*reinterpret_cast<const __half2*>(&c2.y)),
                             make_float2(q3.z, q3.w), acc1);

                const float r = (acc0.x + acc1.x) + (acc0.y + acc1.y);
                s_out[gl * 32 + (lane ^ (gl & 31))] = r;   // conflict-free swizzle
            }
        }
        __syncthreads();

        // Coalesced write-out: warp = batch row, lane = consecutive g.
        {
            const int gbase = c * GPB;
            float* orow = out + (size_t)(bt * BT + w) * G + gbase;
            #pragma unroll
            for (int it = 0; it < 8; it++) {
                const int gl = it * 32 + lane;
                if (gbase + gl < G)
                    orow[gl] = s_out[gl * 32 + (w ^ lane)];
            }
        }

        if (!has_next) break;
        __pipeline_wait_prior(0);
        __syncthreads();
        buf ^= 1;
        c = cn;
    }
}

extern "C" void kernel_launch(void* const* d_in, const int* in_sizes, int n_in,
                              void* d_out, int out_size) {
    const float* features = (const float*)d_in[0];   // [B, T]
    const float* w1       = (const float*)d_in[1];   // [T, K]
    const float* b1       = (const float*)d_in[2];   // [T, K]
    const float* w2       = (const float*)d_in[3];   // [T, K, K]
    const float* b2       = (const float*)d_in[4];   // [T, K]
    const float* w3       = (const float*)d_in[5];   // [G, EPG, K]
    const float* b3       = (const float*)d_in[6];   // [G]
    const int*   edge     = (const int*)  d_in[7];   // [G, EPG]
    float*       out      = (float*)d_out;           // [B, G]

    prep_kernel<<<H2_BLOCKS + PACK_BLOCKS, BLKP>>>(
        features, (const float4*)w1, (const float4*)b1,
        (const float4*)w2, (const float4*)b2, edge, w3, b3);

    const int smem = 131072 + 32768 + 32768;   // 192 KB
    cudaFuncSetAttribute(gather_kernel,
                         cudaFuncAttributeMaxDynamicSharedMemorySize, smem);
    dim3 gridB(NSPLIT, NBT);
    gather_kernel<<<gridB, BLKG, smem>>>(out);
}